// round 4
// baseline (speedup 1.0000x reference)
#include <cuda_runtime.h>
#include <math.h>

#define GD 64
#define SD 32
#define NV (GD*GD*GD)
#define NP (SD*SD*SD)

// ---------------- device scratch ----------------
__device__ float g_prob[NV*16];
__device__ float g_hs[8][NV*16];           // per-stage conv1 outputs (stages overlap!)
__device__ float g_h1[NP*16];
__device__ unsigned char g_occx[NV];
__device__ unsigned char g_pocc[NP];
__device__ unsigned char g_min[NV];
__device__ int g_list_in[8][NV];
__device__ int g_list_out[8][NV/4];
__device__ int g_cnt_in[8];
__device__ int g_cnt_out[8];

struct P1 {
    const float* w[8]; const float* b[8];
    const float* w20; const float* b20;
    int blk0[8];
    unsigned lut3[5][24];
    unsigned lut5[2][3];
};
struct P2 {
    const float* w[8]; const float* b[8];
    int blk0[8];
    unsigned lut3[5][24];
    unsigned lut5[2][3];
};

// ---------------- occupancy ----------------
__global__ void k_occ(const float* __restrict__ x) {
    int v = blockIdx.x*256 + threadIdx.x;
    if (v < 8) { g_cnt_in[v] = 0; g_cnt_out[v] = 0; }
    if (v < NV) g_occx[v] = (x[v] > 0.f) ? 1 : 0;
}

__global__ void k_pocc() {
    int p = blockIdx.x*256 + threadIdx.x;
    if (p >= NP) return;
    int px = p>>10, py = (p>>5)&31, pz = p&31;
    int bx = px<<1, by = py<<1, bz = pz<<1;
    unsigned char o = 0;
    #pragma unroll
    for (int a=0;a<2;a++)
    #pragma unroll
    for (int b=0;b<2;b++)
    #pragma unroll
    for (int c=0;c<2;c++)
        o |= g_occx[((bx+a)<<12)|((by+b)<<6)|(bz+c)];
    g_pocc[p] = o;
}

// ---------------- fused: mask/lists/labels (blocks 0..1023) + FEL conv1 (1024..1151) ----------------
__global__ void k_maskfel1(float* __restrict__ out,
                           const float* __restrict__ wf1, const float* __restrict__ bf1) {
    __shared__ int scnt[16];
    __shared__ int sbase[16];
    __shared__ float swf[432];
    __shared__ float sbf[16];
    int tid = threadIdx.x;
    if (blockIdx.x < 1024) {
        if (tid < 16) scnt[tid] = 0;
        __syncthreads();
        int v = blockIdx.x*256 + tid;
        int x = v>>12, y = (v>>6)&63, z = v&63;
        const int LUT[8] = {0,5,4,3,4,2,1,5};
        int gid = LUT[((x&1)<<2)|((y&1)<<1)|(z&1)];
        int mid = ((x>>1)+(y>>1)+(z>>1)) % 3;
        bool O = g_pocc[((x>>1)<<10)|((y>>1)<<5)|(z>>1)] != 0;
        bool X = g_occx[v] != 0;
        bool g0 = (gid == 0);

        bool bi[8], bo[8];
        bi[0] = O && g0 && (mid==0);
        bi[1] = (O && g0 && mid==1) || (X && g0 && mid==0);
        bi[2] = (X && g0 && mid<2)  || (O && g0 && mid==2);
        bi[3] = (X && g0)      || (O && gid==1);
        bi[4] = (X && gid<=1)  || (O && gid==2);
        bi[5] = (X && gid<=2)  || (O && gid==3);
        bi[6] = (X && gid<=3)  || (O && gid==4);
        bi[7] = (X && gid<=4)  || (O && gid==5);
        bo[0] = O && g0 && mid==0;
        bo[1] = O && g0 && mid==1;
        bo[2] = O && g0 && mid==2;
        #pragma unroll
        for (int s=3;s<8;s++) bo[s] = O && (gid == s-2);

        unsigned char mb = 0;
        int rin[8], rout[8];
        #pragma unroll
        for (int s=0;s<8;s++) {
            if (bi[s]) { mb |= (1u<<s); rin[s]  = atomicAdd(&scnt[s],   1); }
            if (bo[s]) {               rout[s] = atomicAdd(&scnt[8+s], 1); }
        }
        g_min[v] = mb;
        __syncthreads();
        if (tid < 16) {
            int c = scnt[tid];
            sbase[tid] = c ? atomicAdd(tid<8 ? &g_cnt_in[tid] : &g_cnt_out[tid-8], c) : 0;
        }
        __syncthreads();
        #pragma unroll
        for (int s=0;s<8;s++) {
            if (bi[s]) g_list_in[s][sbase[s]   + rin[s]]  = v;
            if (bo[s]) g_list_out[s][sbase[8+s]+ rout[s]] = v;
        }
        #pragma unroll
        for (int s=0;s<8;s++) out[(s<<18)+v] = 0.f;
        #pragma unroll
        for (int s=0;s<8;s++) {
            bool lab = (s<3) ? (X && g0 && mid==s) : (X && gid==(s-2));
            out[((8+s)<<18)+v] = lab ? 1.f : 0.f;
        }
    } else {
        for (int i=tid;i<432;i+=256) swf[i]=wf1[i];
        if (tid<16) sbf[tid]=bf1[tid];
        __syncthreads();
        int p = (blockIdx.x-1024)*256 + tid;
        if (!g_pocc[p]) return;
        int px=p>>10, py=(p>>5)&31, pz=p&31;
        float acc[16];
        #pragma unroll
        for (int c=0;c<16;c++) acc[c]=sbf[c];
        for (int dx=-1;dx<=1;dx++){ int nx=px+dx; if ((unsigned)nx>=32u) continue;
        for (int dy=-1;dy<=1;dy++){ int ny=py+dy; if ((unsigned)ny>=32u) continue;
        for (int dz=-1;dz<=1;dz++){ int nz=pz+dz; if ((unsigned)nz>=32u) continue;
            if (!g_pocc[(nx<<10)|(ny<<5)|nz]) continue;
            int d = ((dx+1)*3+(dy+1))*3+(dz+1);
            const float* wr = swf + d*16;
            #pragma unroll
            for (int c=0;c<16;c++) acc[c] += wr[c];
        }}}
        float* o = g_h1 + p*16;
        #pragma unroll
        for (int c=0;c<16;c++) o[c] = fmaxf(acc[c],0.f);
    }
}

// ---------------- fused: FEL conv2 + generative upsample ----------------
__global__ void k_fel2up(const float* __restrict__ w, const float* __restrict__ b,
                         const float* __restrict__ wup, const float* __restrict__ bup) {
    __shared__ float sw[27*256];
    __shared__ float su[8*256];
    __shared__ float sb2[16];
    __shared__ float sbu[16];
    int tid = threadIdx.x;
    for (int i=tid;i<6912;i+=256) sw[i]=w[i];
    for (int i=tid;i<2048;i+=256) su[i]=wup[i];
    if (tid<16) { sb2[tid]=b[tid]; sbu[tid]=bup[tid]; }
    __syncthreads();
    int p = blockIdx.x*256 + tid;
    if (!g_pocc[p]) return;
    float acc[16];
    #pragma unroll
    for (int c=0;c<16;c++) acc[c]=sb2[c];
    int px=p>>10, py=(p>>5)&31, pz=p&31;
    for (int dx=-1;dx<=1;dx++){ int nx=px+dx; if ((unsigned)nx>=32u) continue;
    for (int dy=-1;dy<=1;dy++){ int ny=py+dy; if ((unsigned)ny>=32u) continue;
    for (int dz=-1;dz<=1;dz++){ int nz=pz+dz; if ((unsigned)nz>=32u) continue;
        int nv = (nx<<10)|(ny<<5)|nz;
        if (!g_pocc[nv]) continue;
        int d = ((dx+1)*3+(dy+1))*3+(dz+1);
        const float* hp = g_h1 + nv*16;
        const float* wr = sw + d*256;
        #pragma unroll
        for (int cin=0;cin<16;cin++){
            float vv = hp[cin];
            #pragma unroll
            for (int c=0;c<16;c++) acc[c] += vv*wr[cin*16+c];
        }
    }}}
    int cx = px<<1, cy = py<<1, cz = pz<<1;
    #pragma unroll
    for (int o=0;o<8;o++) {
        float co[16];
        #pragma unroll
        for (int c=0;c<16;c++) co[c]=sbu[c];
        const float* wo = su + o*256;
        #pragma unroll
        for (int cin=0;cin<16;cin++){
            float vv = acc[cin];
            #pragma unroll
            for (int c=0;c<16;c++) co[c] += vv*wo[cin*16+c];
        }
        int v = ((cx+(o>>2))<<12) | ((cy+((o>>1)&1))<<6) | (cz+(o&1));
        float4* pv = (float4*)(g_prob + v*16);
        pv[0] = make_float4(co[0],co[1],co[2],co[3]);
        pv[1] = make_float4(co[4],co[5],co[6],co[7]);
        pv[2] = make_float4(co[8],co[9],co[10],co[11]);
        pv[3] = make_float4(co[12],co[13],co[14],co[15]);
    }
}

// ---------------- conv helpers ----------------
__device__ __forceinline__ int tap_dv(int t, int sc) {
    return sc * ((t/9-1)*4096 + ((t/3)%3-1)*64 + (t%3-1));
}

__device__ __forceinline__ void fma_g(float vv, const float4* pw,
                                      float4& a0, float4& a1, float4& a2, float4& a3) {
    float4 w0=pw[0], w1=pw[1], w2=pw[2], w3=pw[3];
    a0.x+=vv*w0.x; a0.y+=vv*w0.y; a0.z+=vv*w0.z; a0.w+=vv*w0.w;
    a1.x+=vv*w1.x; a1.y+=vv*w1.y; a1.z+=vv*w1.z; a1.w+=vv*w1.w;
    a2.x+=vv*w2.x; a2.y+=vv*w2.y; a2.z+=vv*w2.z; a2.w+=vv*w2.w;
    a3.x+=vv*w3.x; a3.y+=vv*w3.y; a3.z+=vv*w3.z; a3.w+=vv*w3.w;
}

template<int SC>
__device__ __forceinline__ unsigned live_mask(int v, int s, unsigned cand) {
    int x=v>>12, y=(v>>6)&63, z=v&63;
    unsigned live=0;
    #pragma unroll
    for (int t=0;t<27;t++) {
        if (cand & (1u<<t)) {
            int nx=x+SC*(t/9-1), ny=y+SC*((t/3)%3-1), nz=z+SC*(t%3-1);
            if ((unsigned)(nx|ny|nz) < 64u) {
                int nv=(nx<<12)|(ny<<6)|nz;
                live |= ((unsigned)((g_min[nv]>>s)&1))<<t;
            }
        }
    }
    return live;
}

template<int SC>
__device__ __forceinline__ void conv1_core(int v, unsigned live, const float* sw,
                                           float4& a0, float4& a1, float4& a2, float4& a3) {
    unsigned m = live;
    if (!m) return;
    int t = __ffs(m)-1; m &= m-1;
    const float4* pc = (const float4*)(g_prob + (v + tap_dv(t,SC))*16);
    float4 c0=pc[0], c1=pc[1], c2=pc[2], c3=pc[3];
    for (;;) {
        int t2 = -1;
        float4 n0,n1,n2,n3;
        if (m) {
            t2 = __ffs(m)-1; m &= m-1;
            const float4* pn = (const float4*)(g_prob + (v + tap_dv(t2,SC))*16);
            n0=pn[0]; n1=pn[1]; n2=pn[2]; n3=pn[3];
        }
        const float4* pw = (const float4*)(sw + t*256);
        fma_g(c0.x, pw+ 0, a0,a1,a2,a3); fma_g(c0.y, pw+ 4, a0,a1,a2,a3);
        fma_g(c0.z, pw+ 8, a0,a1,a2,a3); fma_g(c0.w, pw+12, a0,a1,a2,a3);
        fma_g(c1.x, pw+16, a0,a1,a2,a3); fma_g(c1.y, pw+20, a0,a1,a2,a3);
        fma_g(c1.z, pw+24, a0,a1,a2,a3); fma_g(c1.w, pw+28, a0,a1,a2,a3);
        fma_g(c2.x, pw+32, a0,a1,a2,a3); fma_g(c2.y, pw+36, a0,a1,a2,a3);
        fma_g(c2.z, pw+40, a0,a1,a2,a3); fma_g(c2.w, pw+44, a0,a1,a2,a3);
        fma_g(c3.x, pw+48, a0,a1,a2,a3); fma_g(c3.y, pw+52, a0,a1,a2,a3);
        fma_g(c3.z, pw+56, a0,a1,a2,a3); fma_g(c3.w, pw+60, a0,a1,a2,a3);
        if (t2 < 0) break;
        t = t2; c0=n0; c1=n1; c2=n2; c3=n3;
    }
}

// ---------------- conv1, all 8 stages in one kernel ----------------
__global__ void __launch_bounds__(256) k_conv1_all(P1 P, float* __restrict__ out) {
    __shared__ float sw[27*256];
    int bx = blockIdx.x, tid = threadIdx.x;
    int s = 0;
    #pragma unroll
    for (int i=1;i<8;i++) s += (bx >= P.blk0[i]);
    int rb = bx - P.blk0[s];
    int cnt = g_cnt_in[s];
    if (rb*256 >= cnt) return;

    if (s == 0) {
        if (tid < 256) sw[tid] = P.w[0][13*256 + tid];
        if (tid < 16)  sw[256+tid] = P.w20[13*16 + tid];
        if (tid < 16)  sw[272+tid] = P.b[0][tid];
        __syncthreads();
        int idx = rb*256 + tid;
        if (idx >= cnt) return;
        int v = g_list_in[0][idx];
        const float4* pin = (const float4*)(g_prob + v*16);
        float4 i0=pin[0], i1=pin[1], i2=pin[2], i3=pin[3];
        float in[16] = {i0.x,i0.y,i0.z,i0.w, i1.x,i1.y,i1.z,i1.w,
                        i2.x,i2.y,i2.z,i2.w, i3.x,i3.y,i3.z,i3.w};
        float a[16];
        #pragma unroll
        for (int c=0;c<16;c++) a[c]=sw[272+c];
        #pragma unroll
        for (int cin=0;cin<16;cin++){
            float vv = in[cin];
            #pragma unroll
            for (int c=0;c<16;c++) a[c] += vv*sw[cin*16+c];
        }
        float acc = P.b20[0];
        #pragma unroll
        for (int c=0;c<16;c++) acc += fmaxf(a[c],0.f)*sw[256+c];
        out[v] = 1.f/(1.f + expf(-acc));
        return;
    }

    bool is5 = (s==1 || s==2);
    const float* w = P.w[s];
    if (is5) {
        for (int i=tid;i<6912;i+=256) {
            int t=i>>8, c=i&255;
            int a=t/9, bb=(t/3)%3, cc=t%3;
            sw[i] = w[(((2*a)*5+2*bb)*5+2*cc)*256 + c];
        }
    } else {
        for (int i=tid;i<6912;i+=256) sw[i]=w[i];
    }
    __syncthreads();
    int idx = rb*256 + tid;
    if (idx >= cnt) return;
    int v = g_list_in[s][idx];
    int x=v>>12, y=(v>>6)&63, z=v&63;
    int mid = ((x>>1)+(y>>1)+(z>>1)) % 3;
    unsigned cand;
    if (is5) cand = P.lut5[s-1][mid];
    else {
        int par = ((x&1)<<2)|((y&1)<<1)|(z&1);
        cand = P.lut3[s-3][par*3+mid];
    }
    const float4* b4 = (const float4*)P.b[s];
    float4 a0=b4[0], a1=b4[1], a2=b4[2], a3=b4[3];
    if (is5) {
        unsigned live = live_mask<2>(v, s, cand);
        conv1_core<2>(v, live, sw, a0,a1,a2,a3);
    } else {
        unsigned live = live_mask<1>(v, s, cand);
        conv1_core<1>(v, live, sw, a0,a1,a2,a3);
    }
    a0.x=fmaxf(a0.x,0.f); a0.y=fmaxf(a0.y,0.f); a0.z=fmaxf(a0.z,0.f); a0.w=fmaxf(a0.w,0.f);
    a1.x=fmaxf(a1.x,0.f); a1.y=fmaxf(a1.y,0.f); a1.z=fmaxf(a1.z,0.f); a1.w=fmaxf(a1.w,0.f);
    a2.x=fmaxf(a2.x,0.f); a2.y=fmaxf(a2.y,0.f); a2.z=fmaxf(a2.z,0.f); a2.w=fmaxf(a2.w,0.f);
    a3.x=fmaxf(a3.x,0.f); a3.y=fmaxf(a3.y,0.f); a3.z=fmaxf(a3.z,0.f); a3.w=fmaxf(a3.w,0.f);
    float4* ph = (float4*)(&g_hs[s][v*16]);
    ph[0]=a0; ph[1]=a1; ph[2]=a2; ph[3]=a3;
}

// ---------------- conv2 ----------------
template<int SC>
__device__ __forceinline__ float conv2_core(const float* __restrict__ hbase, int v,
                                            unsigned live, const float* sw) {
    float acc = 0.f;
    unsigned m = live;
    if (!m) return acc;
    int t = __ffs(m)-1; m &= m-1;
    const float4* pc = (const float4*)(hbase + (v + tap_dv(t,SC))*16);
    float4 c0=pc[0], c1=pc[1], c2=pc[2], c3=pc[3];
    for (;;) {
        int t2 = -1;
        float4 n0,n1,n2,n3;
        if (m) {
            t2 = __ffs(m)-1; m &= m-1;
            const float4* pn = (const float4*)(hbase + (v + tap_dv(t2,SC))*16);
            n0=pn[0]; n1=pn[1]; n2=pn[2]; n3=pn[3];
        }
        const float* wr = sw + t*16;
        acc += c0.x*wr[0] + c0.y*wr[1] + c0.z*wr[2] + c0.w*wr[3]
             + c1.x*wr[4] + c1.y*wr[5] + c1.z*wr[6] + c1.w*wr[7]
             + c2.x*wr[8] + c2.y*wr[9] + c2.z*wr[10]+ c2.w*wr[11]
             + c3.x*wr[12]+ c3.y*wr[13]+ c3.z*wr[14]+ c3.w*wr[15];
        if (t2 < 0) break;
        t = t2; c0=n0; c1=n1; c2=n2; c3=n3;
    }
    return acc;
}

__global__ void __launch_bounds__(256) k_conv2_all(P2 P, float* __restrict__ out) {
    __shared__ float sw[27*16];
    int bx = blockIdx.x, tid = threadIdx.x;
    int s = 1;
    #pragma unroll
    for (int i=2;i<8;i++) s += (bx >= P.blk0[i]);
    int rb = bx - P.blk0[s];
    int cnt = g_cnt_out[s];
    if (rb*256 >= cnt) return;
    bool is5 = (s==1 || s==2);
    const float* w = P.w[s];
    if (is5) {
        for (int i=tid;i<432;i+=256) {
            int t=i>>4, c=i&15;
            int a=t/9, bb=(t/3)%3, cc=t%3;
            sw[i] = w[(((2*a)*5+2*bb)*5+2*cc)*16 + c];
        }
    } else {
        for (int i=tid;i<432;i+=256) sw[i]=w[i];
    }
    __syncthreads();
    int idx = rb*256 + tid;
    if (idx >= cnt) return;
    int v = g_list_out[s][idx];
    int x=v>>12, y=(v>>6)&63, z=v&63;
    int mid = ((x>>1)+(y>>1)+(z>>1)) % 3;
    unsigned cand;
    if (is5) cand = P.lut5[s-1][mid];
    else {
        int par = ((x&1)<<2)|((y&1)<<1)|(z&1);
        cand = P.lut3[s-3][par*3+mid];
    }
    const float* hbase = g_hs[s];
    float acc = P.b[s][0];
    if (is5) acc += conv2_core<2>(hbase, v, live_mask<2>(v, s, cand), sw);
    else     acc += conv2_core<1>(hbase, v, live_mask<1>(v, s, cand), sw);
    out[(s<<18)+v] = 1.f/(1.f + expf(-acc));
}

// ---------------- host-side LUT construction ----------------
static const int GIDH[8] = {0,5,4,3,4,2,1,5};

static bool cand_in(int s, int par, int mid) {
    int gid = GIDH[par];
    if (s==0) return gid==0 && mid==0;
    if (s==1) return gid==0 && mid<2;
    if (s==2) return gid==0;
    return gid <= s-2;
}

static int middelta(int pc, int d) {
    if (d==-2) return -1;
    if (d== 2) return  1;
    if (d== 0) return  0;
    if (pc==0) return d==-1 ? -1 : 0;
    return d==1 ? 1 : 0;
}

static void build24(int s, unsigned* L) {
    for (int par=0;par<8;par++) for (int mid=0;mid<3;mid++) {
        unsigned m=0;
        for (int t=0;t<27;t++) {
            int dx=t/9-1, dy=(t/3)%3-1, dz=t%3-1;
            int pn = par ^ ((((dx&1))<<2)|(((dy&1))<<1)|(dz&1));
            int dm = middelta((par>>2)&1,dx)+middelta((par>>1)&1,dy)+middelta(par&1,dz);
            int mn = ((mid+dm)%3+3)%3;
            if (cand_in(s,pn,mn)) m |= 1u<<t;
        }
        L[par*3+mid]=m;
    }
}

static void build3(int s, unsigned* L) {
    for (int mid=0;mid<3;mid++) {
        unsigned m=0;
        for (int t=0;t<27;t++) {
            int dx=2*(t/9-1), dy=2*((t/3)%3-1), dz=2*(t%3-1);
            int dm=(dx+dy+dz)/2;
            int mn=((mid+dm)%3+3)%3;
            if (cand_in(s,0,mn)) m |= 1u<<t;
        }
        L[mid]=m;
    }
}

// ---------------- launch ----------------
extern "C" void kernel_launch(void* const* d_in, const int* in_sizes, int n_in,
                              void* d_out, int out_size) {
    const float* x      = (const float*)d_in[0];
    const float* w_fel1 = (const float*)d_in[3];
    const float* b_fel1 = (const float*)d_in[4];
    const float* w_fel2 = (const float*)d_in[5];
    const float* b_fel2 = (const float*)d_in[6];
    const float* w_up   = (const float*)d_in[7];
    const float* b_up   = (const float*)d_in[8];
    const float* wc1    = (const float*)d_in[9];
    const float* bc1    = (const float*)d_in[10];
    const float* wc2    = (const float*)d_in[11];
    const float* bc2    = (const float*)d_in[12];
    const float* wl1    = (const float*)d_in[13];
    const float* bl1    = (const float*)d_in[14];
    const float* wl2    = (const float*)d_in[15];
    const float* bl2    = (const float*)d_in[16];
    float* out = (float*)d_out;

    const int inB[8]  = {10922,21846,32768,65536,98304,131072,196608,262144};
    const int outB[8] = {10922,10923,10923,32768,32768,32768,65536,65536};

    P1 p1; P2 p2;
    for (int s=0;s<8;s++) {
        if (s==1 || s==2) {
            p1.w[s] = wl1 + (s-1)*125*256; p1.b[s] = bl1 + (s-1)*16;
            p2.w[s] = wl2 + (s-1)*125*16;  p2.b[s] = bl2 + (s-1);
            build3(s, p1.lut5[s-1]);
            for (int i=0;i<3;i++) p2.lut5[s-1][i] = p1.lut5[s-1][i];
        } else {
            int k = (s==0) ? 0 : (s-2);
            p1.w[s] = wc1 + k*27*256; p1.b[s] = bc1 + k*16;
            p2.w[s] = wc2 + k*27*16;  p2.b[s] = bc2 + k;
            if (s>=3) {
                build24(s, p1.lut3[s-3]);
                for (int i=0;i<24;i++) p2.lut3[s-3][i] = p1.lut3[s-3][i];
            }
        }
    }
    p1.w20 = wc2; p1.b20 = bc2;

    int acc1 = 0, acc2 = 0;
    for (int s=0;s<8;s++) { p1.blk0[s] = acc1; acc1 += (inB[s]+255)/256; }
    p2.blk0[0] = 0;
    for (int s=1;s<8;s++) { p2.blk0[s] = acc2; acc2 += (outB[s]+255)/256; }

    k_occ<<<1024,256>>>(x);
    k_pocc<<<128,256>>>();
    k_maskfel1<<<1152,256>>>(out, w_fel1, b_fel1);
    k_fel2up<<<128,256>>>(w_fel2, b_fel2, w_up, b_up);
    k_conv1_all<<<acc1,256>>>(p1, out);
    k_conv2_all<<<acc2,256>>>(p2, out);
}

// round 6
// speedup vs baseline: 1.9920x; 1.9920x over previous
#include <cuda_runtime.h>
#include <math.h>

#define GD 64
#define SD 32
#define NV (GD*GD*GD)
#define NP (SD*SD*SD)

// ---------------- device scratch ----------------
__device__ float g_prob[NV*16];
__device__ float g_hs[8][NV*16];           // per-stage conv1 outputs (stages run concurrently)
__device__ float g_h1[NP*16];
__device__ float g_h2[NP*16];
__device__ unsigned char g_occx[NV];
__device__ unsigned char g_pocc[NP];
__device__ unsigned char g_min[NV];
__device__ int g_list_in[8][NV];
__device__ int g_list_out[8][NV/4];
__device__ int g_cnt_in[8];
__device__ int g_cnt_out[8];

struct P1 {
    const float* w[8]; const float* b[8];
    const float* w20; const float* b20;
    int blk0[8];
    unsigned lut3[5][24];
    unsigned lut5[2][3];
};
struct P2 {
    const float* w[8]; const float* b[8];
    int blk0[8];
    unsigned lut3[5][24];
    unsigned lut5[2][3];
};

// ---------------- init: occ + pocc + counters, parent-indexed ----------------
__global__ void k_init(const float* __restrict__ x) {
    int p = blockIdx.x*256 + threadIdx.x;
    if (p < 8) { g_cnt_in[p] = 0; g_cnt_out[p] = 0; }
    if (p >= NP) return;
    int px = p>>10, py = (p>>5)&31, pz = p&31;
    int bx = px<<1, by = py<<1, bz = pz<<1;
    unsigned char o = 0;
    #pragma unroll
    for (int a=0;a<2;a++)
    #pragma unroll
    for (int b=0;b<2;b++)
    #pragma unroll
    for (int c=0;c<2;c++) {
        int v = ((bx+a)<<12)|((by+b)<<6)|(bz+c);
        unsigned char oc = (x[v] > 0.f) ? 1 : 0;
        g_occx[v] = oc;
        o |= oc;
    }
    g_pocc[p] = o;
}

// ---------------- fused: mask/lists/labels (blocks 0..1023) + FEL conv1 (1024..1151) ----------------
__global__ void k_maskfel1(float* __restrict__ out,
                           const float* __restrict__ wf1, const float* __restrict__ bf1) {
    __shared__ int scnt[16];
    __shared__ int sbase[16];
    __shared__ float swf[432];
    __shared__ float sbf[16];
    int tid = threadIdx.x;
    if (blockIdx.x < 1024) {
        if (tid < 16) scnt[tid] = 0;
        __syncthreads();
        int v = blockIdx.x*256 + tid;
        int x = v>>12, y = (v>>6)&63, z = v&63;
        const int LUT[8] = {0,5,4,3,4,2,1,5};
        int gid = LUT[((x&1)<<2)|((y&1)<<1)|(z&1)];
        int mid = ((x>>1)+(y>>1)+(z>>1)) % 3;
        bool O = g_pocc[((x>>1)<<10)|((y>>1)<<5)|(z>>1)] != 0;
        bool X = g_occx[v] != 0;
        bool g0 = (gid == 0);

        bool bi[8], bo[8];
        bi[0] = O && g0 && (mid==0);
        bi[1] = (O && g0 && mid==1) || (X && g0 && mid==0);
        bi[2] = (X && g0 && mid<2)  || (O && g0 && mid==2);
        bi[3] = (X && g0)      || (O && gid==1);
        bi[4] = (X && gid<=1)  || (O && gid==2);
        bi[5] = (X && gid<=2)  || (O && gid==3);
        bi[6] = (X && gid<=3)  || (O && gid==4);
        bi[7] = (X && gid<=4)  || (O && gid==5);
        bo[0] = O && g0 && mid==0;
        bo[1] = O && g0 && mid==1;
        bo[2] = O && g0 && mid==2;
        #pragma unroll
        for (int s=3;s<8;s++) bo[s] = O && (gid == s-2);

        unsigned char mb = 0;
        int rin[8], rout[8];
        #pragma unroll
        for (int s=0;s<8;s++) {
            if (bi[s]) { mb |= (1u<<s); rin[s]  = atomicAdd(&scnt[s],   1); }
            if (bo[s]) {               rout[s] = atomicAdd(&scnt[8+s], 1); }
        }
        g_min[v] = mb;
        __syncthreads();
        if (tid < 16) {
            int c = scnt[tid];
            sbase[tid] = c ? atomicAdd(tid<8 ? &g_cnt_in[tid] : &g_cnt_out[tid-8], c) : 0;
        }
        __syncthreads();
        #pragma unroll
        for (int s=0;s<8;s++) {
            if (bi[s]) g_list_in[s][sbase[s]   + rin[s]]  = v;
            if (bo[s]) g_list_out[s][sbase[8+s]+ rout[s]] = v;
        }
        #pragma unroll
        for (int s=0;s<8;s++) out[(s<<18)+v] = 0.f;
        #pragma unroll
        for (int s=0;s<8;s++) {
            bool lab = (s<3) ? (X && g0 && mid==s) : (X && gid==(s-2));
            out[((8+s)<<18)+v] = lab ? 1.f : 0.f;
        }
    } else {
        for (int i=tid;i<432;i+=256) swf[i]=wf1[i];
        if (tid<16) sbf[tid]=bf1[tid];
        __syncthreads();
        int p = (blockIdx.x-1024)*256 + tid;
        if (!g_pocc[p]) return;
        int px=p>>10, py=(p>>5)&31, pz=p&31;
        float acc[16];
        #pragma unroll
        for (int c=0;c<16;c++) acc[c]=sbf[c];
        for (int dx=-1;dx<=1;dx++){ int nx=px+dx; if ((unsigned)nx>=32u) continue;
        for (int dy=-1;dy<=1;dy++){ int ny=py+dy; if ((unsigned)ny>=32u) continue;
        for (int dz=-1;dz<=1;dz++){ int nz=pz+dz; if ((unsigned)nz>=32u) continue;
            if (!g_pocc[(nx<<10)|(ny<<5)|nz]) continue;
            int d = ((dx+1)*3+(dy+1))*3+(dz+1);
            const float* wr = swf + d*16;
            #pragma unroll
            for (int c=0;c<16;c++) acc[c] += wr[c];
        }}}
        float* o = g_h1 + p*16;
        #pragma unroll
        for (int c=0;c<16;c++) o[c] = fmaxf(acc[c],0.f);
    }
}

// ---------------- FEL conv2: 16->16 ----------------
__global__ void k_fel2(const float* __restrict__ w, const float* __restrict__ b) {
    __shared__ float sw[27*256];
    int tid = threadIdx.x;
    for (int i=tid;i<6912;i+=blockDim.x) sw[i]=w[i];
    __syncthreads();
    int p = blockIdx.x*blockDim.x + tid;
    if (p >= NP) return;
    if (!g_pocc[p]) return;
    float acc[16];
    #pragma unroll
    for (int c=0;c<16;c++) acc[c]=b[c];
    int px=p>>10, py=(p>>5)&31, pz=p&31;
    for (int dx=-1;dx<=1;dx++){ int nx=px+dx; if ((unsigned)nx>=32u) continue;
    for (int dy=-1;dy<=1;dy++){ int ny=py+dy; if ((unsigned)ny>=32u) continue;
    for (int dz=-1;dz<=1;dz++){ int nz=pz+dz; if ((unsigned)nz>=32u) continue;
        int nv = (nx<<10)|(ny<<5)|nz;
        if (!g_pocc[nv]) continue;
        int d = ((dx+1)*3+(dy+1))*3+(dz+1);
        const float* hp = g_h1 + nv*16;
        const float* wr = sw + d*256;
        #pragma unroll
        for (int cin=0;cin<16;cin++){
            float vv = hp[cin];
            #pragma unroll
            for (int c=0;c<16;c++) acc[c] += vv*wr[cin*16+c];
        }
    }}}
    float* o = g_h2 + p*16;
    #pragma unroll
    for (int c=0;c<16;c++) o[c]=acc[c];
}

// ---------------- generative upsample ----------------
__global__ void k_up(const float* __restrict__ wup, const float* __restrict__ bup) {
    __shared__ float sw[8*256];
    __shared__ float sb[16];
    int tid = threadIdx.x;
    for (int i=tid;i<2048;i+=blockDim.x) sw[i]=wup[i];
    if (tid<16) sb[tid]=bup[tid];
    __syncthreads();
    int v = blockIdx.x*blockDim.x + tid;
    if (v >= NV) return;
    int x=v>>12, y=(v>>6)&63, z=v&63;
    int p = ((x>>1)<<10)|((y>>1)<<5)|(z>>1);
    float* po = g_prob + v*16;
    if (!g_pocc[p]) {
        #pragma unroll
        for (int c=0;c<16;c++) po[c]=0.f;
        return;
    }
    int o = ((x&1)<<2)|((y&1)<<1)|(z&1);
    float acc[16];
    #pragma unroll
    for (int c=0;c<16;c++) acc[c]=sb[c];
    const float* hp = g_h2 + p*16;
    const float* wo = sw + o*256;
    #pragma unroll
    for (int cin=0;cin<16;cin++){
        float vv = hp[cin];
        #pragma unroll
        for (int c=0;c<16;c++) acc[c] += vv*wo[cin*16+c];
    }
    #pragma unroll
    for (int c=0;c<16;c++) po[c]=acc[c];
}

// ---------------- conv1, all 8 stages in one launch (R2 loop bodies) ----------------
__global__ void __launch_bounds__(256) k_conv1_all(P1 P, float* __restrict__ out) {
    __shared__ float sw[27*256 + 64];
    int bx = blockIdx.x, tid = threadIdx.x;
    int s = 0;
    #pragma unroll
    for (int i=1;i<8;i++) s += (bx >= P.blk0[i]);
    int rb = bx - P.blk0[s];
    int cnt = g_cnt_in[s];
    if (rb*256 >= cnt) return;

    if (s == 0) {
        // fused pointwise coder: conv1 center tap -> relu -> conv2 center tap -> sigmoid
        if (tid < 256) sw[tid] = P.w[0][13*256 + tid];
        if (tid < 16)  sw[6912+tid] = P.w20[13*16 + tid];
        if (tid < 16)  sw[6928+tid] = P.b[0][tid];
        __syncthreads();
        int idx = rb*256 + tid;
        if (idx >= cnt) return;
        int v = g_list_in[0][idx];
        const float4* pin = (const float4*)(g_prob + v*16);
        float4 i0=pin[0], i1=pin[1], i2=pin[2], i3=pin[3];
        float in[16] = {i0.x,i0.y,i0.z,i0.w, i1.x,i1.y,i1.z,i1.w,
                        i2.x,i2.y,i2.z,i2.w, i3.x,i3.y,i3.z,i3.w};
        float a[16];
        #pragma unroll
        for (int c=0;c<16;c++) a[c]=sw[6928+c];
        #pragma unroll
        for (int cin=0;cin<16;cin++){
            float vv = in[cin];
            #pragma unroll
            for (int c=0;c<16;c++) a[c] += vv*sw[cin*16+c];
        }
        float acc = P.b20[0];
        #pragma unroll
        for (int c=0;c<16;c++) acc += fmaxf(a[c],0.f)*sw[6912+c];
        out[v] = 1.f/(1.f + expf(-acc));
        return;
    }

    bool is5 = (s==1 || s==2);
    const float* w = P.w[s];
    if (is5) {
        for (int i=tid;i<6912;i+=256) {
            int t=i>>8, c=i&255;
            int a=t/9, bb=(t/3)%3, cc=t%3;
            sw[i] = w[(((2*a)*5+2*bb)*5+2*cc)*256 + c];
        }
    } else {
        for (int i=tid;i<6912;i+=256) sw[i]=w[i];
    }
    __syncthreads();
    int idx = rb*256 + tid;
    if (idx >= cnt) return;
    int v = g_list_in[s][idx];
    int x=v>>12, y=(v>>6)&63, z=v&63;
    int mid = ((x>>1)+(y>>1)+(z>>1)) % 3;
    unsigned m;
    if (is5) m = P.lut5[s-1][mid];
    else {
        int par = ((x&1)<<2)|((y&1)<<1)|(z&1);
        m = P.lut3[s-3][par*3+mid];
    }
    int sc = is5 ? 2 : 1;
    const float4* b4 = (const float4*)P.b[s];
    float4 a0=b4[0], a1=b4[1], a2=b4[2], a3=b4[3];
    while (m) {
        int t = __ffs(m)-1; m &= m-1;
        int nx=x+sc*(t/9-1), ny=y+sc*((t/3)%3-1), nz=z+sc*(t%3-1);
        if ((unsigned)(nx|ny|nz) >= 64u) continue;
        int nv = (nx<<12)|(ny<<6)|nz;
        if (!((g_min[nv]>>s)&1)) continue;
        const float4* pin = (const float4*)(g_prob + nv*16);
        float4 i0=pin[0], i1=pin[1], i2=pin[2], i3=pin[3];
        float in[16] = {i0.x,i0.y,i0.z,i0.w, i1.x,i1.y,i1.z,i1.w,
                        i2.x,i2.y,i2.z,i2.w, i3.x,i3.y,i3.z,i3.w};
        const float4* pw = (const float4*)(sw + t*256);
        #pragma unroll
        for (int c=0;c<16;c++){
            float vv = in[c];
            float4 w0=pw[c*4+0], w1=pw[c*4+1], w2=pw[c*4+2], w3=pw[c*4+3];
            a0.x += vv*w0.x; a0.y += vv*w0.y; a0.z += vv*w0.z; a0.w += vv*w0.w;
            a1.x += vv*w1.x; a1.y += vv*w1.y; a1.z += vv*w1.z; a1.w += vv*w1.w;
            a2.x += vv*w2.x; a2.y += vv*w2.y; a2.z += vv*w2.z; a2.w += vv*w2.w;
            a3.x += vv*w3.x; a3.y += vv*w3.y; a3.z += vv*w3.z; a3.w += vv*w3.w;
        }
    }
    a0.x=fmaxf(a0.x,0.f); a0.y=fmaxf(a0.y,0.f); a0.z=fmaxf(a0.z,0.f); a0.w=fmaxf(a0.w,0.f);
    a1.x=fmaxf(a1.x,0.f); a1.y=fmaxf(a1.y,0.f); a1.z=fmaxf(a1.z,0.f); a1.w=fmaxf(a1.w,0.f);
    a2.x=fmaxf(a2.x,0.f); a2.y=fmaxf(a2.y,0.f); a2.z=fmaxf(a2.z,0.f); a2.w=fmaxf(a2.w,0.f);
    a3.x=fmaxf(a3.x,0.f); a3.y=fmaxf(a3.y,0.f); a3.z=fmaxf(a3.z,0.f); a3.w=fmaxf(a3.w,0.f);
    float4* ph = (float4*)(&g_hs[s][v*16]);
    ph[0]=a0; ph[1]=a1; ph[2]=a2; ph[3]=a3;
}

// ---------------- conv2, stages 1..7 in one launch (R2 loop bodies) ----------------
__global__ void __launch_bounds__(256) k_conv2_all(P2 P, float* __restrict__ out) {
    __shared__ float sw[27*16];
    int bx = blockIdx.x, tid = threadIdx.x;
    int s = 1;
    #pragma unroll
    for (int i=2;i<8;i++) s += (bx >= P.blk0[i]);
    int rb = bx - P.blk0[s];
    int cnt = g_cnt_out[s];
    if (rb*256 >= cnt) return;
    bool is5 = (s==1 || s==2);
    const float* w = P.w[s];
    if (is5) {
        for (int i=tid;i<432;i+=256) {
            int t=i>>4, c=i&15;
            int a=t/9, bb=(t/3)%3, cc=t%3;
            sw[i] = w[(((2*a)*5+2*bb)*5+2*cc)*16 + c];
        }
    } else {
        for (int i=tid;i<432;i+=256) sw[i]=w[i];
    }
    __syncthreads();
    int idx = rb*256 + tid;
    if (idx >= cnt) return;
    int v = g_list_out[s][idx];
    int x=v>>12, y=(v>>6)&63, z=v&63;
    int mid = ((x>>1)+(y>>1)+(z>>1)) % 3;
    unsigned m;
    if (is5) m = P.lut5[s-1][mid];
    else {
        int par = ((x&1)<<2)|((y&1)<<1)|(z&1);
        m = P.lut3[s-3][par*3+mid];
    }
    int sc = is5 ? 2 : 1;
    const float* hbase = g_hs[s];
    float acc = P.b[s][0];
    while (m) {
        int t = __ffs(m)-1; m &= m-1;
        int nx=x+sc*(t/9-1), ny=y+sc*((t/3)%3-1), nz=z+sc*(t%3-1);
        if ((unsigned)(nx|ny|nz) >= 64u) continue;
        int nv = (nx<<12)|(ny<<6)|nz;
        if (!((g_min[nv]>>s)&1)) continue;
        const float* hp = hbase + nv*16;
        const float* wr = sw + t*16;
        #pragma unroll
        for (int cin=0;cin<16;cin++) acc += hp[cin]*wr[cin];
    }
    out[(s<<18)+v] = 1.f/(1.f + expf(-acc));
}

// ---------------- host-side LUT construction ----------------
static const int GIDH[8] = {0,5,4,3,4,2,1,5};

static bool cand_in(int s, int par, int mid) {
    int gid = GIDH[par];
    if (s==0) return gid==0 && mid==0;
    if (s==1) return gid==0 && mid<2;
    if (s==2) return gid==0;
    return gid <= s-2;
}

static int middelta(int pc, int d) {
    if (d==-2) return -1;
    if (d== 2) return  1;
    if (d== 0) return  0;
    if (pc==0) return d==-1 ? -1 : 0;
    return d==1 ? 1 : 0;
}

static void build24(int s, unsigned* L) {
    for (int par=0;par<8;par++) for (int mid=0;mid<3;mid++) {
        unsigned m=0;
        for (int t=0;t<27;t++) {
            int dx=t/9-1, dy=(t/3)%3-1, dz=t%3-1;
            int pn = par ^ ((((dx&1))<<2)|(((dy&1))<<1)|(dz&1));
            int dm = middelta((par>>2)&1,dx)+middelta((par>>1)&1,dy)+middelta(par&1,dz);
            int mn = ((mid+dm)%3+3)%3;
            if (cand_in(s,pn,mn)) m |= 1u<<t;
        }
        L[par*3+mid]=m;
    }
}

static void build3(int s, unsigned* L) {
    for (int mid=0;mid<3;mid++) {
        unsigned m=0;
        for (int t=0;t<27;t++) {
            int dx=2*(t/9-1), dy=2*((t/3)%3-1), dz=2*(t%3-1);
            int dm=(dx+dy+dz)/2;
            int mn=((mid+dm)%3+3)%3;
            if (cand_in(s,0,mn)) m |= 1u<<t;
        }
        L[mid]=m;
    }
}

// ---------------- launch: 6 launches, single stream ----------------
extern "C" void kernel_launch(void* const* d_in, const int* in_sizes, int n_in,
                              void* d_out, int out_size) {
    const float* x      = (const float*)d_in[0];
    const float* w_fel1 = (const float*)d_in[3];
    const float* b_fel1 = (const float*)d_in[4];
    const float* w_fel2 = (const float*)d_in[5];
    const float* b_fel2 = (const float*)d_in[6];
    const float* w_up   = (const float*)d_in[7];
    const float* b_up   = (const float*)d_in[8];
    const float* wc1    = (const float*)d_in[9];
    const float* bc1    = (const float*)d_in[10];
    const float* wc2    = (const float*)d_in[11];
    const float* bc2    = (const float*)d_in[12];
    const float* wl1    = (const float*)d_in[13];
    const float* bl1    = (const float*)d_in[14];
    const float* wl2    = (const float*)d_in[15];
    const float* bl2    = (const float*)d_in[16];
    float* out = (float*)d_out;

    const int inB[8]  = {10922,21846,32768,65536,98304,131072,196608,262144};
    const int outB[8] = {10922,10923,10923,32768,32768,32768,65536,65536};

    P1 p1; P2 p2;
    for (int s=0;s<8;s++) {
        if (s==1 || s==2) {
            p1.w[s] = wl1 + (s-1)*125*256; p1.b[s] = bl1 + (s-1)*16;
            p2.w[s] = wl2 + (s-1)*125*16;  p2.b[s] = bl2 + (s-1);
            build3(s, p1.lut5[s-1]);
            for (int i=0;i<3;i++) p2.lut5[s-1][i] = p1.lut5[s-1][i];
        } else {
            int k = (s==0) ? 0 : (s-2);
            p1.w[s] = wc1 + k*27*256; p1.b[s] = bc1 + k*16;
            p2.w[s] = wc2 + k*27*16;  p2.b[s] = bc2 + k;
            if (s>=3) {
                build24(s, p1.lut3[s-3]);
                for (int i=0;i<24;i++) p2.lut3[s-3][i] = p1.lut3[s-3][i];
            }
        }
    }
    p1.w20 = wc2; p1.b20 = bc2;

    int acc1 = 0, acc2 = 0;
    for (int s=0;s<8;s++) { p1.blk0[s] = acc1; acc1 += (inB[s]+255)/256; }
    p2.blk0[0] = 0;
    for (int s=1;s<8;s++) { p2.blk0[s] = acc2; acc2 += (outB[s]+255)/256; }

    k_init<<<128,256>>>(x);
    k_maskfel1<<<1152,256>>>(out, w_fel1, b_fel1);
    k_fel2<<<128,256>>>(w_fel2, b_fel2);
    k_up<<<1024,256>>>(w_up, b_up);
    k_conv1_all<<<acc1,256>>>(p1, out);
    k_conv2_all<<<acc2,256>>>(p2, out);
}

// round 7
// speedup vs baseline: 2.3648x; 1.1872x over previous
#include <cuda_runtime.h>
#include <math.h>

#define GD 64
#define SD 32
#define NV (GD*GD*GD)
#define NP (SD*SD*SD)
#define CSTRIDE 10944           // per-(stage,class) list region (>= 10923, 64-aligned)
#define CH 43                   // chunks per class list: ceil(10923/256)

// ---------------- device scratch ----------------
__device__ float g_prob[NV*16];
__device__ float g_hs[8][NV*16];
__device__ float g_h1[NP*16];
__device__ float g_h2[NP*16];
__device__ unsigned char g_occx[NV];
__device__ unsigned char g_pocc[NP];
__device__ unsigned char g_min[NV];
__device__ int g_list_in_c[192*CSTRIDE];
__device__ int g_list_out_c[192*CSTRIDE];
__device__ int g_cnt_in_c[192];
__device__ int g_cnt_out_c[192];

struct K1 {
    const float* w[8]; const float* b[8];
    const float* w20; const float* b20;
    int n_ent;
    int lid[80]; unsigned cand[80]; unsigned char es[80];
};
struct K2 {
    const float* w[8]; const float* b[8];
    int n_ent;
    int lid[32]; unsigned cand[32]; unsigned char es[32];
};

// ---------------- init: occ + pocc + counters ----------------
__global__ void k_init(const float* __restrict__ x) {
    int p = blockIdx.x*256 + threadIdx.x;
    if (p < 192) { g_cnt_in_c[p] = 0; g_cnt_out_c[p] = 0; }
    if (p >= NP) return;
    int px = p>>10, py = (p>>5)&31, pz = p&31;
    int bx = px<<1, by = py<<1, bz = pz<<1;
    unsigned char o = 0;
    #pragma unroll
    for (int a=0;a<2;a++)
    #pragma unroll
    for (int b=0;b<2;b++)
    #pragma unroll
    for (int c=0;c<2;c++) {
        int v = ((bx+a)<<12)|((by+b)<<6)|(bz+c);
        unsigned char oc = (x[v] > 0.f) ? 1 : 0;
        g_occx[v] = oc;
        o |= oc;
    }
    g_pocc[p] = o;
}

// ---------------- fused: mask/class-lists/labels (0..1023) + FEL conv1 (1024..1151) ----------------
__global__ void k_maskfel1(float* __restrict__ out,
                           const float* __restrict__ wf1, const float* __restrict__ bf1) {
    __shared__ int scnt[384];
    __shared__ int sbase[384];
    __shared__ float swf[432];
    __shared__ float sbf[16];
    int tid = threadIdx.x;
    if (blockIdx.x < 1024) {
        for (int i=tid;i<384;i+=256) scnt[i]=0;
        __syncthreads();
        int v = blockIdx.x*256 + tid;
        int x = v>>12, y = (v>>6)&63, z = v&63;
        const int LUT[8] = {0,5,4,3,4,2,1,5};
        int par = ((x&1)<<2)|((y&1)<<1)|(z&1);
        int gid = LUT[par];
        int mid = ((x>>1)+(y>>1)+(z>>1)) % 3;
        int cls = par*3 + mid;
        bool O = g_pocc[((x>>1)<<10)|((y>>1)<<5)|(z>>1)] != 0;
        bool X = g_occx[v] != 0;
        bool g0 = (gid == 0);

        bool bi[8], bo[8];
        bi[0] = O && g0 && (mid==0);
        bi[1] = (O && g0 && mid==1) || (X && g0 && mid==0);
        bi[2] = (X && g0 && mid<2)  || (O && g0 && mid==2);
        bi[3] = (X && g0)      || (O && gid==1);
        bi[4] = (X && gid<=1)  || (O && gid==2);
        bi[5] = (X && gid<=2)  || (O && gid==3);
        bi[6] = (X && gid<=3)  || (O && gid==4);
        bi[7] = (X && gid<=4)  || (O && gid==5);
        bo[0] = O && g0 && mid==0;
        bo[1] = O && g0 && mid==1;
        bo[2] = O && g0 && mid==2;
        #pragma unroll
        for (int s=3;s<8;s++) bo[s] = O && (gid == s-2);

        unsigned char mb = 0;
        int rin[8], rout[8];
        #pragma unroll
        for (int s=0;s<8;s++) {
            if (bi[s]) { mb |= (1u<<s); rin[s]  = atomicAdd(&scnt[s*24+cls],     1); }
            if (bo[s]) {               rout[s] = atomicAdd(&scnt[192+s*24+cls], 1); }
        }
        g_min[v] = mb;
        __syncthreads();
        for (int i=tid;i<384;i+=256) {
            int c = scnt[i];
            sbase[i] = c ? atomicAdd(i<192 ? &g_cnt_in_c[i] : &g_cnt_out_c[i-192], c) : 0;
        }
        __syncthreads();
        #pragma unroll
        for (int s=0;s<8;s++) {
            if (bi[s]) g_list_in_c [(s*24+cls)*CSTRIDE + sbase[s*24+cls]     + rin[s]]  = v;
            if (bo[s]) g_list_out_c[(s*24+cls)*CSTRIDE + sbase[192+s*24+cls] + rout[s]] = v;
        }
        #pragma unroll
        for (int s=0;s<8;s++) out[(s<<18)+v] = 0.f;
        #pragma unroll
        for (int s=0;s<8;s++) {
            bool lab = (s<3) ? (X && g0 && mid==s) : (X && gid==(s-2));
            out[((8+s)<<18)+v] = lab ? 1.f : 0.f;
        }
    } else {
        for (int i=tid;i<432;i+=256) swf[i]=wf1[i];
        if (tid<16) sbf[tid]=bf1[tid];
        __syncthreads();
        int p = (blockIdx.x-1024)*256 + tid;
        if (!g_pocc[p]) return;
        int px=p>>10, py=(p>>5)&31, pz=p&31;
        float acc[16];
        #pragma unroll
        for (int c=0;c<16;c++) acc[c]=sbf[c];
        for (int dx=-1;dx<=1;dx++){ int nx=px+dx; if ((unsigned)nx>=32u) continue;
        for (int dy=-1;dy<=1;dy++){ int ny=py+dy; if ((unsigned)ny>=32u) continue;
        for (int dz=-1;dz<=1;dz++){ int nz=pz+dz; if ((unsigned)nz>=32u) continue;
            if (!g_pocc[(nx<<10)|(ny<<5)|nz]) continue;
            int d = ((dx+1)*3+(dy+1))*3+(dz+1);
            const float* wr = swf + d*16;
            #pragma unroll
            for (int c=0;c<16;c++) acc[c] += wr[c];
        }}}
        float* o = g_h1 + p*16;
        #pragma unroll
        for (int c=0;c<16;c++) o[c] = fmaxf(acc[c],0.f);
    }
}

// ---------------- FEL conv2 ----------------
__global__ void k_fel2(const float* __restrict__ w, const float* __restrict__ b) {
    __shared__ float sw[27*256];
    int tid = threadIdx.x;
    for (int i=tid;i<6912;i+=blockDim.x) sw[i]=w[i];
    __syncthreads();
    int p = blockIdx.x*blockDim.x + tid;
    if (p >= NP) return;
    if (!g_pocc[p]) return;
    float acc[16];
    #pragma unroll
    for (int c=0;c<16;c++) acc[c]=b[c];
    int px=p>>10, py=(p>>5)&31, pz=p&31;
    for (int dx=-1;dx<=1;dx++){ int nx=px+dx; if ((unsigned)nx>=32u) continue;
    for (int dy=-1;dy<=1;dy++){ int ny=py+dy; if ((unsigned)ny>=32u) continue;
    for (int dz=-1;dz<=1;dz++){ int nz=pz+dz; if ((unsigned)nz>=32u) continue;
        int nv = (nx<<10)|(ny<<5)|nz;
        if (!g_pocc[nv]) continue;
        int d = ((dx+1)*3+(dy+1))*3+(dz+1);
        const float* hp = g_h1 + nv*16;
        const float* wr = sw + d*256;
        #pragma unroll
        for (int cin=0;cin<16;cin++){
            float vv = hp[cin];
            #pragma unroll
            for (int c=0;c<16;c++) acc[c] += vv*wr[cin*16+c];
        }
    }}}
    float* o = g_h2 + p*16;
    #pragma unroll
    for (int c=0;c<16;c++) o[c]=acc[c];
}

// ---------------- generative upsample ----------------
__global__ void k_up(const float* __restrict__ wup, const float* __restrict__ bup) {
    __shared__ float sw[8*256];
    __shared__ float sb[16];
    int tid = threadIdx.x;
    for (int i=tid;i<2048;i+=blockDim.x) sw[i]=wup[i];
    if (tid<16) sb[tid]=bup[tid];
    __syncthreads();
    int v = blockIdx.x*blockDim.x + tid;
    if (v >= NV) return;
    int x=v>>12, y=(v>>6)&63, z=v&63;
    int p = ((x>>1)<<10)|((y>>1)<<5)|(z>>1);
    float* po = g_prob + v*16;
    if (!g_pocc[p]) {
        #pragma unroll
        for (int c=0;c<16;c++) po[c]=0.f;
        return;
    }
    int o = ((x&1)<<2)|((y&1)<<1)|(z&1);
    float acc[16];
    #pragma unroll
    for (int c=0;c<16;c++) acc[c]=sb[c];
    const float* hp = g_h2 + p*16;
    const float* wo = sw + o*256;
    #pragma unroll
    for (int cin=0;cin<16;cin++){
        float vv = hp[cin];
        #pragma unroll
        for (int c=0;c<16;c++) acc[c] += vv*wo[cin*16+c];
    }
    #pragma unroll
    for (int c=0;c<16;c++) po[c]=acc[c];
}

// ---------------- conv1: class-uniform blocks, predicated taps ----------------
__global__ void __launch_bounds__(256) k_conv1_all(K1 P, float* __restrict__ out) {
    int e = blockIdx.x / CH, ch = blockIdx.x % CH;
    int s = P.es[e];
    int lid = P.lid[e];
    int cnt = g_cnt_in_c[lid];
    if (ch*256 >= cnt) return;
    __shared__ float sw[6944];
    int tid = threadIdx.x;

    if (s == 0) {
        if (tid < 256) sw[tid] = P.w[0][13*256 + tid];
        if (tid < 16)  sw[6912+tid] = P.w20[13*16 + tid];
        if (tid < 16)  sw[6928+tid] = P.b[0][tid];
        __syncthreads();
        int idx = ch*256 + tid;
        if (idx >= cnt) return;
        int v = g_list_in_c[lid*CSTRIDE + idx];
        const float4* pin = (const float4*)(g_prob + v*16);
        float4 i0=pin[0], i1=pin[1], i2=pin[2], i3=pin[3];
        float in[16] = {i0.x,i0.y,i0.z,i0.w, i1.x,i1.y,i1.z,i1.w,
                        i2.x,i2.y,i2.z,i2.w, i3.x,i3.y,i3.z,i3.w};
        float a[16];
        #pragma unroll
        for (int c=0;c<16;c++) a[c]=sw[6928+c];
        #pragma unroll
        for (int cin=0;cin<16;cin++){
            float vv = in[cin];
            #pragma unroll
            for (int c=0;c<16;c++) a[c] += vv*sw[cin*16+c];
        }
        float acc = P.b20[0];
        #pragma unroll
        for (int c=0;c<16;c++) acc += fmaxf(a[c],0.f)*sw[6912+c];
        out[v] = 1.f/(1.f + expf(-acc));
        return;
    }

    bool is5 = (s==1 || s==2);
    const float* w = P.w[s];
    if (is5) {
        for (int i=tid;i<6912;i+=256) {
            int t=i>>8, c=i&255;
            int a=t/9, bb=(t/3)%3, cc=t%3;
            sw[i] = w[(((2*a)*5+2*bb)*5+2*cc)*256 + c];
        }
    } else {
        for (int i=tid;i<6912;i+=256) sw[i]=w[i];
    }
    __syncthreads();
    int idx = ch*256 + tid;
    if (idx >= cnt) return;
    int v = g_list_in_c[lid*CSTRIDE + idx];
    int x=v>>12, y=(v>>6)&63, z=v&63;
    int sc = is5 ? 2 : 1;
    unsigned m = P.cand[e];           // uniform across block -> no divergence
    const float4* b4 = (const float4*)P.b[s];
    float4 a0=b4[0], a1=b4[1], a2=b4[2], a3=b4[3];
    while (m) {
        int t = __ffs(m)-1; m &= m-1;
        int nx = x + sc*(t/9-1), ny = y + sc*((t/3)%3-1), nz = z + sc*(t%3-1);
        bool inb = ((unsigned)(nx|ny|nz) < 64u);
        int nvc = ((nx&63)<<12)|((ny&63)<<6)|(nz&63);
        float sel = (inb && ((g_min[nvc]>>s)&1)) ? 1.f : 0.f;
        const float4* pin = (const float4*)(g_prob + nvc*16);
        float4 i0=pin[0], i1=pin[1], i2=pin[2], i3=pin[3];
        float in[16] = {sel*i0.x,sel*i0.y,sel*i0.z,sel*i0.w, sel*i1.x,sel*i1.y,sel*i1.z,sel*i1.w,
                        sel*i2.x,sel*i2.y,sel*i2.z,sel*i2.w, sel*i3.x,sel*i3.y,sel*i3.z,sel*i3.w};
        const float4* pw = (const float4*)(sw + t*256);
        #pragma unroll
        for (int c=0;c<16;c++){
            float vv = in[c];
            float4 w0=pw[c*4+0], w1=pw[c*4+1], w2=pw[c*4+2], w3=pw[c*4+3];
            a0.x += vv*w0.x; a0.y += vv*w0.y; a0.z += vv*w0.z; a0.w += vv*w0.w;
            a1.x += vv*w1.x; a1.y += vv*w1.y; a1.z += vv*w1.z; a1.w += vv*w1.w;
            a2.x += vv*w2.x; a2.y += vv*w2.y; a2.z += vv*w2.z; a2.w += vv*w2.w;
            a3.x += vv*w3.x; a3.y += vv*w3.y; a3.z += vv*w3.z; a3.w += vv*w3.w;
        }
    }
    a0.x=fmaxf(a0.x,0.f); a0.y=fmaxf(a0.y,0.f); a0.z=fmaxf(a0.z,0.f); a0.w=fmaxf(a0.w,0.f);
    a1.x=fmaxf(a1.x,0.f); a1.y=fmaxf(a1.y,0.f); a1.z=fmaxf(a1.z,0.f); a1.w=fmaxf(a1.w,0.f);
    a2.x=fmaxf(a2.x,0.f); a2.y=fmaxf(a2.y,0.f); a2.z=fmaxf(a2.z,0.f); a2.w=fmaxf(a2.w,0.f);
    a3.x=fmaxf(a3.x,0.f); a3.y=fmaxf(a3.y,0.f); a3.z=fmaxf(a3.z,0.f); a3.w=fmaxf(a3.w,0.f);
    float4* ph = (float4*)(&g_hs[s][v*16]);
    ph[0]=a0; ph[1]=a1; ph[2]=a2; ph[3]=a3;
}

// ---------------- conv2: class-uniform blocks, predicated taps ----------------
__global__ void __launch_bounds__(256) k_conv2_all(K2 P, float* __restrict__ out) {
    int e = blockIdx.x / CH, ch = blockIdx.x % CH;
    int s = P.es[e];
    int lid = P.lid[e];
    int cnt = g_cnt_out_c[lid];
    if (ch*256 >= cnt) return;
    __shared__ float sw[432];
    int tid = threadIdx.x;
    bool is5 = (s==1 || s==2);
    const float* w = P.w[s];
    if (is5) {
        for (int i=tid;i<432;i+=256) {
            int t=i>>4, c=i&15;
            int a=t/9, bb=(t/3)%3, cc=t%3;
            sw[i] = w[(((2*a)*5+2*bb)*5+2*cc)*16 + c];
        }
    } else {
        for (int i=tid;i<432;i+=256) sw[i]=w[i];
    }
    __syncthreads();
    int idx = ch*256 + tid;
    if (idx >= cnt) return;
    int v = g_list_out_c[lid*CSTRIDE + idx];
    int x=v>>12, y=(v>>6)&63, z=v&63;
    int sc = is5 ? 2 : 1;
    unsigned m = P.cand[e];
    const float* hbase = g_hs[s];
    float acc = P.b[s][0];
    while (m) {
        int t = __ffs(m)-1; m &= m-1;
        int nx = x + sc*(t/9-1), ny = y + sc*((t/3)%3-1), nz = z + sc*(t%3-1);
        bool inb = ((unsigned)(nx|ny|nz) < 64u);
        int nvc = ((nx&63)<<12)|((ny&63)<<6)|(nz&63);
        float sel = (inb && ((g_min[nvc]>>s)&1)) ? 1.f : 0.f;
        const float4* pc = (const float4*)(hbase + nvc*16);
        float4 c0=pc[0], c1=pc[1], c2=pc[2], c3=pc[3];
        const float* wr = sw + t*16;
        float d = c0.x*wr[0] + c0.y*wr[1] + c0.z*wr[2] + c0.w*wr[3]
                + c1.x*wr[4] + c1.y*wr[5] + c1.z*wr[6] + c1.w*wr[7]
                + c2.x*wr[8] + c2.y*wr[9] + c2.z*wr[10]+ c2.w*wr[11]
                + c3.x*wr[12]+ c3.y*wr[13]+ c3.z*wr[14]+ c3.w*wr[15];
        acc += sel*d;
    }
    out[(s<<18)+v] = 1.f/(1.f + expf(-acc));
}

// ---------------- host-side class/LUT construction ----------------
static const int GIDH[8] = {0,5,4,3,4,2,1,5};

static bool cand_in(int s, int par, int mid) {
    int gid = GIDH[par];
    if (s==0) return gid==0 && mid==0;
    if (s==1) return gid==0 && mid<2;
    if (s==2) return gid==0;
    return gid <= s-2;
}

static int middelta(int pc, int d) {
    if (d==-2) return -1;
    if (d== 2) return  1;
    if (d== 0) return  0;
    if (pc==0) return d==-1 ? -1 : 0;
    return d==1 ? 1 : 0;
}

static unsigned mask3(int s, int par, int mid) {
    unsigned m=0;
    for (int t=0;t<27;t++) {
        int dx=t/9-1, dy=(t/3)%3-1, dz=t%3-1;
        int pn = par ^ ((((dx&1))<<2)|(((dy&1))<<1)|(dz&1));
        int dm = middelta((par>>2)&1,dx)+middelta((par>>1)&1,dy)+middelta(par&1,dz);
        int mn = ((mid+dm)%3+3)%3;
        if (cand_in(s,pn,mn)) m |= 1u<<t;
    }
    return m;
}

static unsigned mask5(int s, int mid) {
    unsigned m=0;
    for (int t=0;t<27;t++) {
        int dx=2*(t/9-1), dy=2*((t/3)%3-1), dz=2*(t%3-1);
        int dm=(dx+dy+dz)/2;
        int mn=((mid+dm)%3+3)%3;
        if (cand_in(s,0,mn)) m |= 1u<<t;
    }
    return m;
}

static bool out_class(int s, int par, int mid) {
    int gid = GIDH[par];
    if (s<3) return gid==0 && mid==s;
    return gid == s-2;
}

// ---------------- launch ----------------
extern "C" void kernel_launch(void* const* d_in, const int* in_sizes, int n_in,
                              void* d_out, int out_size) {
    const float* x      = (const float*)d_in[0];
    const float* w_fel1 = (const float*)d_in[3];
    const float* b_fel1 = (const float*)d_in[4];
    const float* w_fel2 = (const float*)d_in[5];
    const float* b_fel2 = (const float*)d_in[6];
    const float* w_up   = (const float*)d_in[7];
    const float* b_up   = (const float*)d_in[8];
    const float* wc1    = (const float*)d_in[9];
    const float* bc1    = (const float*)d_in[10];
    const float* wc2    = (const float*)d_in[11];
    const float* bc2    = (const float*)d_in[12];
    const float* wl1    = (const float*)d_in[13];
    const float* bl1    = (const float*)d_in[14];
    const float* wl2    = (const float*)d_in[15];
    const float* bl2    = (const float*)d_in[16];
    float* out = (float*)d_out;

    K1 p1; K2 p2;
    for (int s=0;s<8;s++) {
        if (s==1 || s==2) {
            p1.w[s] = wl1 + (s-1)*125*256; p1.b[s] = bl1 + (s-1)*16;
            p2.w[s] = wl2 + (s-1)*125*16;  p2.b[s] = bl2 + (s-1);
        } else {
            int k = (s==0) ? 0 : (s-2);
            p1.w[s] = wc1 + k*27*256; p1.b[s] = bc1 + k*16;
            p2.w[s] = wc2 + k*27*16;  p2.b[s] = bc2 + k;
        }
    }
    p1.w20 = wc2; p1.b20 = bc2;

    // conv1 entries: one per statically-possible (stage, class)
    int n1 = 0;
    for (int s=0;s<8;s++)
        for (int par=0;par<8;par++)
            for (int mid=0;mid<3;mid++)
                if (cand_in(s,par,mid)) {
                    p1.es[n1]  = (unsigned char)s;
                    p1.lid[n1] = s*24 + par*3 + mid;
                    p1.cand[n1] = (s==0) ? (1u<<13)
                                : (s<=2) ? mask5(s,mid)
                                         : mask3(s,par,mid);
                    n1++;
                }
    p1.n_ent = n1;

    // conv2 entries: stages 1..7 output classes (stage 0 fused into conv1)
    int n2 = 0;
    for (int s=1;s<8;s++)
        for (int par=0;par<8;par++)
            for (int mid=0;mid<3;mid++)
                if (out_class(s,par,mid)) {
                    p2.es[n2]  = (unsigned char)s;
                    p2.lid[n2] = s*24 + par*3 + mid;
                    p2.cand[n2] = (s<=2) ? mask5(s,mid) : mask3(s,par,mid);
                    n2++;
                }
    p2.n_ent = n2;

    k_init<<<128,256>>>(x);
    k_maskfel1<<<1152,256>>>(out, w_fel1, b_fel1);
    k_fel2<<<128,256>>>(w_fel2, b_fel2);
    k_up<<<1024,256>>>(w_up, b_up);
    k_conv1_all<<<n1*CH,256>>>(p1, out);
    k_conv2_all<<<n2*CH,256>>>(p2, out);
}